// round 1
// baseline (speedup 1.0000x reference)
#include <cuda_runtime.h>
#include <cuda_bf16.h>
#include <cstdint>

// Fused SIREN MLP: 3 -> 256 -> 256 -> 256 -> 256 -> 3
// h0 = sin(30*(W0 x + b0)); h_{l+1} = sin(W h_l + b); out = W4 h3 + b4
//
// Strategy (round 1, fp32 baseline with f32x2 packed FMA):
//  - one CTA = 64 points, 256 threads (8 warps)
//  - activations live in SMEM, layout h[neuron][point], stride 68 floats
//    (16B-aligned rows, conflict-free broadcast reads, <=4-way write conflicts)
//  - thread t handles neurons {t&127, (t&127)+128} and points [32*(t>>7), +32)
//  - inner GEMM: fma.rn.f32x2 (2 points packed per FMA) -> 2x fp32 rate
//  - weights stream from global (L2-resident, 256KB/layer)

#define HID 256
#define PTILE 64
#define HS 68              // smem row stride in floats (68*4=272B, 16B aligned)
#define NTHREADS 256

typedef unsigned long long ull;

__device__ __forceinline__ ull fma2(ull a, ull b, ull c) {
    ull d;
    asm("fma.rn.f32x2 %0, %1, %2, %3;" : "=l"(d) : "l"(a), "l"(b), "l"(c));
    return d;
}

__device__ __forceinline__ ull pack2(float v) {
    ull d;
    asm("mov.b64 %0, {%1, %1};" : "=l"(d) : "f"(v));
    return d;
}

// One hidden GEMM layer + bias + sin.  hin/hout: [256][HS] in smem.
__device__ __forceinline__ void hidden_layer(
    const float* __restrict__ W, const float* __restrict__ b,
    const float* __restrict__ hin, float* __restrict__ hout,
    int og, int pbase)
{
    ull acc[2][16];
#pragma unroll
    for (int n = 0; n < 2; n++)
#pragma unroll
        for (int j = 0; j < 16; j++) acc[n][j] = 0ull;

    const float* wpa = W + og * HID;
    const float* wpb = W + (og + 128) * HID;

#pragma unroll 2
    for (int i = 0; i < HID; i += 4) {
        float4 wa = *reinterpret_cast<const float4*>(wpa + i);
        float4 wb = *reinterpret_cast<const float4*>(wpb + i);
        const float wav[4] = {wa.x, wa.y, wa.z, wa.w};
        const float wbv[4] = {wb.x, wb.y, wb.z, wb.w};
#pragma unroll
        for (int d = 0; d < 4; d++) {
            ull wa2 = pack2(wav[d]);
            ull wb2 = pack2(wbv[d]);
            const ulonglong2* hrow =
                reinterpret_cast<const ulonglong2*>(hin + (i + d) * HS + pbase);
#pragma unroll
            for (int j = 0; j < 8; j++) {
                ulonglong2 hv = hrow[j];
                acc[0][2 * j]     = fma2(wa2, hv.x, acc[0][2 * j]);
                acc[0][2 * j + 1] = fma2(wa2, hv.y, acc[0][2 * j + 1]);
                acc[1][2 * j]     = fma2(wb2, hv.x, acc[1][2 * j]);
                acc[1][2 * j + 1] = fma2(wb2, hv.y, acc[1][2 * j + 1]);
            }
        }
    }

    // epilogue: bias + sin, write transposed layout h[o][p]
#pragma unroll
    for (int n = 0; n < 2; n++) {
        int o = og + n * 128;
        float bb = __ldg(b + o);
        float* orow = hout + o * HS + pbase;
#pragma unroll
        for (int j = 0; j < 16; j++) {
            unsigned lo32 = (unsigned)(acc[n][j] & 0xffffffffull);
            unsigned hi32 = (unsigned)(acc[n][j] >> 32);
            float s0 = sinf(__uint_as_float(lo32) + bb);
            float s1 = sinf(__uint_as_float(hi32) + bb);
            *reinterpret_cast<float2*>(orow + 2 * j) = make_float2(s0, s1);
        }
    }
}

__global__ void __launch_bounds__(NTHREADS, 1) siren_fused_kernel(
    const float* __restrict__ x,
    const float* __restrict__ W0, const float* __restrict__ b0,
    const float* __restrict__ W1, const float* __restrict__ b1,
    const float* __restrict__ W2, const float* __restrict__ b2,
    const float* __restrict__ W3, const float* __restrict__ b3,
    const float* __restrict__ W4, const float* __restrict__ b4,
    float* __restrict__ out, int npts)
{
    extern __shared__ float sm[];
    float* hA = sm;                       // [256][HS]
    float* hB = sm + HID * HS;            // [256][HS]
    float* xs = sm + 2 * HID * HS;        // [64*3]

    const int tid = threadIdx.x;
    const int og = tid & 127;             // neuron group (2 neurons: og, og+128)
    const int pbase = (tid >> 7) * 32;    // point half-tile
    const int tile0 = blockIdx.x * PTILE;

    // stage x tile (64 points x 3) into smem
    if (tid < PTILE * 3) {
        int idx = tile0 * 3 + tid;
        xs[tid] = (idx < npts * 3) ? x[idx] : 0.0f;
    }
    __syncthreads();

    // ---- layer 0: h = sin(30*(W0 x + b0)) -> hA ----
    {
#pragma unroll
        for (int n = 0; n < 2; n++) {
            int o = og + n * 128;
            float w0 = __ldg(W0 + o * 3 + 0);
            float w1 = __ldg(W0 + o * 3 + 1);
            float w2 = __ldg(W0 + o * 3 + 2);
            float bb = __ldg(b0 + o);
            float* orow = hA + o * HS + pbase;
#pragma unroll 4
            for (int p = 0; p < 32; p += 2) {
                const float* xp = xs + (pbase + p) * 3;
                float z0 = 30.0f * (w0 * xp[0] + w1 * xp[1] + w2 * xp[2] + bb);
                float z1 = 30.0f * (w0 * xp[3] + w1 * xp[4] + w2 * xp[5] + bb);
                *reinterpret_cast<float2*>(orow + p) =
                    make_float2(sinf(z0), sinf(z1));
            }
        }
    }
    __syncthreads();

    // ---- hidden layers ----
    hidden_layer(W1, b1, hA, hB, og, pbase);
    __syncthreads();
    hidden_layer(W2, b2, hB, hA, og, pbase);
    __syncthreads();
    hidden_layer(W3, b3, hA, hB, og, pbase);
    __syncthreads();

    // ---- layer 4: out[p][c] = W4[c] . h3[:,p] + b4[c]  (reads hB) ----
    if (tid < PTILE * 3) {
        int c = tid / PTILE;       // 0..2
        int p = tid % PTILE;       // 0..63
        const float* w = W4 + c * HID;
        float acc = 0.0f;
#pragma unroll 8
        for (int i = 0; i < HID; i += 4) {
            float4 wv = *reinterpret_cast<const float4*>(w + i);
            acc += wv.x * hB[(i + 0) * HS + p];
            acc += wv.y * hB[(i + 1) * HS + p];
            acc += wv.z * hB[(i + 2) * HS + p];
            acc += wv.w * hB[(i + 3) * HS + p];
        }
        int prow = tile0 + p;
        if (prow < npts)
            out[prow * 3 + c] = acc + __ldg(b4 + c);
    }
}

extern "C" void kernel_launch(void* const* d_in, const int* in_sizes, int n_in,
                              void* d_out, int out_size) {
    const float* x  = (const float*)d_in[0];
    const float* W0 = (const float*)d_in[1];
    const float* b0 = (const float*)d_in[2];
    const float* W1 = (const float*)d_in[3];
    const float* b1 = (const float*)d_in[4];
    const float* W2 = (const float*)d_in[5];
    const float* b2 = (const float*)d_in[6];
    const float* W3 = (const float*)d_in[7];
    const float* b3 = (const float*)d_in[8];
    const float* W4 = (const float*)d_in[9];
    const float* b4 = (const float*)d_in[10];
    float* out = (float*)d_out;

    int npts = in_sizes[0] / 3;
    int nblocks = (npts + PTILE - 1) / PTILE;

    size_t smem = (2 * HID * HS + PTILE * 3) * sizeof(float);  // 140,032 B
    cudaFuncSetAttribute(siren_fused_kernel,
                         cudaFuncAttributeMaxDynamicSharedMemorySize,
                         (int)smem);

    siren_fused_kernel<<<nblocks, NTHREADS, smem>>>(
        x, W0, b0, W1, b1, W2, b2, W3, b3, W4, b4, out, npts);
}

// round 2
// speedup vs baseline: 1.0029x; 1.0029x over previous
#include <cuda_runtime.h>
#include <cuda_bf16.h>
#include <cstdint>

// Fused SIREN MLP: 3 -> 256 -> 256 -> 256 -> 256 -> 3
// h0 = sin(30*(W0 x + b0)); h_{l+1} = sin(W h_l + b); out = W4 h3 + b4
//
// Strategy (round 1, fp32 baseline with f32x2 packed FMA):
//  - one CTA = 64 points, 256 threads (8 warps)
//  - activations live in SMEM, layout h[neuron][point], stride 68 floats
//    (16B-aligned rows, conflict-free broadcast reads, <=4-way write conflicts)
//  - thread t handles neurons {t&127, (t&127)+128} and points [32*(t>>7), +32)
//  - inner GEMM: fma.rn.f32x2 (2 points packed per FMA) -> 2x fp32 rate
//  - weights stream from global (L2-resident, 256KB/layer)

#define HID 256
#define PTILE 64
#define HS 68              // smem row stride in floats (68*4=272B, 16B aligned)
#define NTHREADS 256

typedef unsigned long long ull;

__device__ __forceinline__ ull fma2(ull a, ull b, ull c) {
    ull d;
    asm("fma.rn.f32x2 %0, %1, %2, %3;" : "=l"(d) : "l"(a), "l"(b), "l"(c));
    return d;
}

__device__ __forceinline__ ull pack2(float v) {
    ull d;
    asm("mov.b64 %0, {%1, %1};" : "=l"(d) : "f"(v));
    return d;
}

// One hidden GEMM layer + bias + sin.  hin/hout: [256][HS] in smem.
__device__ __forceinline__ void hidden_layer(
    const float* __restrict__ W, const float* __restrict__ b,
    const float* __restrict__ hin, float* __restrict__ hout,
    int og, int pbase)
{
    ull acc[2][16];
#pragma unroll
    for (int n = 0; n < 2; n++)
#pragma unroll
        for (int j = 0; j < 16; j++) acc[n][j] = 0ull;

    const float* wpa = W + og * HID;
    const float* wpb = W + (og + 128) * HID;

#pragma unroll 2
    for (int i = 0; i < HID; i += 4) {
        float4 wa = *reinterpret_cast<const float4*>(wpa + i);
        float4 wb = *reinterpret_cast<const float4*>(wpb + i);
        const float wav[4] = {wa.x, wa.y, wa.z, wa.w};
        const float wbv[4] = {wb.x, wb.y, wb.z, wb.w};
#pragma unroll
        for (int d = 0; d < 4; d++) {
            ull wa2 = pack2(wav[d]);
            ull wb2 = pack2(wbv[d]);
            const ulonglong2* hrow =
                reinterpret_cast<const ulonglong2*>(hin + (i + d) * HS + pbase);
#pragma unroll
            for (int j = 0; j < 8; j++) {
                ulonglong2 hv = hrow[j];
                acc[0][2 * j]     = fma2(wa2, hv.x, acc[0][2 * j]);
                acc[0][2 * j + 1] = fma2(wa2, hv.y, acc[0][2 * j + 1]);
                acc[1][2 * j]     = fma2(wb2, hv.x, acc[1][2 * j]);
                acc[1][2 * j + 1] = fma2(wb2, hv.y, acc[1][2 * j + 1]);
            }
        }
    }

    // epilogue: bias + sin, write transposed layout h[o][p]
#pragma unroll
    for (int n = 0; n < 2; n++) {
        int o = og + n * 128;
        float bb = __ldg(b + o);
        float* orow = hout + o * HS + pbase;
#pragma unroll
        for (int j = 0; j < 16; j++) {
            unsigned lo32 = (unsigned)(acc[n][j] & 0xffffffffull);
            unsigned hi32 = (unsigned)(acc[n][j] >> 32);
            float s0 = sinf(__uint_as_float(lo32) + bb);
            float s1 = sinf(__uint_as_float(hi32) + bb);
            *reinterpret_cast<float2*>(orow + 2 * j) = make_float2(s0, s1);
        }
    }
}

__global__ void __launch_bounds__(NTHREADS, 1) siren_fused_kernel(
    const float* __restrict__ x,
    const float* __restrict__ W0, const float* __restrict__ b0,
    const float* __restrict__ W1, const float* __restrict__ b1,
    const float* __restrict__ W2, const float* __restrict__ b2,
    const float* __restrict__ W3, const float* __restrict__ b3,
    const float* __restrict__ W4, const float* __restrict__ b4,
    float* __restrict__ out, int npts)
{
    extern __shared__ float sm[];
    float* hA = sm;                       // [256][HS]
    float* hB = sm + HID * HS;            // [256][HS]
    float* xs = sm + 2 * HID * HS;        // [64*3]

    const int tid = threadIdx.x;
    const int og = tid & 127;             // neuron group (2 neurons: og, og+128)
    const int pbase = (tid >> 7) * 32;    // point half-tile
    const int tile0 = blockIdx.x * PTILE;

    // stage x tile (64 points x 3) into smem
    if (tid < PTILE * 3) {
        int idx = tile0 * 3 + tid;
        xs[tid] = (idx < npts * 3) ? x[idx] : 0.0f;
    }
    __syncthreads();

    // ---- layer 0: h = sin(30*(W0 x + b0)) -> hA ----
    {
#pragma unroll
        for (int n = 0; n < 2; n++) {
            int o = og + n * 128;
            float w0 = __ldg(W0 + o * 3 + 0);
            float w1 = __ldg(W0 + o * 3 + 1);
            float w2 = __ldg(W0 + o * 3 + 2);
            float bb = __ldg(b0 + o);
            float* orow = hA + o * HS + pbase;
#pragma unroll 4
            for (int p = 0; p < 32; p += 2) {
                const float* xp = xs + (pbase + p) * 3;
                float z0 = 30.0f * (w0 * xp[0] + w1 * xp[1] + w2 * xp[2] + bb);
                float z1 = 30.0f * (w0 * xp[3] + w1 * xp[4] + w2 * xp[5] + bb);
                *reinterpret_cast<float2*>(orow + p) =
                    make_float2(sinf(z0), sinf(z1));
            }
        }
    }
    __syncthreads();

    // ---- hidden layers ----
    hidden_layer(W1, b1, hA, hB, og, pbase);
    __syncthreads();
    hidden_layer(W2, b2, hB, hA, og, pbase);
    __syncthreads();
    hidden_layer(W3, b3, hA, hB, og, pbase);
    __syncthreads();

    // ---- layer 4: out[p][c] = W4[c] . h3[:,p] + b4[c]  (reads hB) ----
    if (tid < PTILE * 3) {
        int c = tid / PTILE;       // 0..2
        int p = tid % PTILE;       // 0..63
        const float* w = W4 + c * HID;
        float acc = 0.0f;
#pragma unroll 8
        for (int i = 0; i < HID; i += 4) {
            float4 wv = *reinterpret_cast<const float4*>(w + i);
            acc += wv.x * hB[(i + 0) * HS + p];
            acc += wv.y * hB[(i + 1) * HS + p];
            acc += wv.z * hB[(i + 2) * HS + p];
            acc += wv.w * hB[(i + 3) * HS + p];
        }
        int prow = tile0 + p;
        if (prow < npts)
            out[prow * 3 + c] = acc + __ldg(b4 + c);
    }
}

extern "C" void kernel_launch(void* const* d_in, const int* in_sizes, int n_in,
                              void* d_out, int out_size) {
    const float* x  = (const float*)d_in[0];
    const float* W0 = (const float*)d_in[1];
    const float* b0 = (const float*)d_in[2];
    const float* W1 = (const float*)d_in[3];
    const float* b1 = (const float*)d_in[4];
    const float* W2 = (const float*)d_in[5];
    const float* b2 = (const float*)d_in[6];
    const float* W3 = (const float*)d_in[7];
    const float* b3 = (const float*)d_in[8];
    const float* W4 = (const float*)d_in[9];
    const float* b4 = (const float*)d_in[10];
    float* out = (float*)d_out;

    int npts = in_sizes[0] / 3;
    int nblocks = (npts + PTILE - 1) / PTILE;

    size_t smem = (2 * HID * HS + PTILE * 3) * sizeof(float);  // 140,032 B
    cudaFuncSetAttribute(siren_fused_kernel,
                         cudaFuncAttributeMaxDynamicSharedMemorySize,
                         (int)smem);

    siren_fused_kernel<<<nblocks, NTHREADS, smem>>>(
        x, W0, b0, W1, b1, W2, b2, W3, b3, W4, b4, out, npts);
}